// round 8
// baseline (speedup 1.0000x reference)
#include <cuda_runtime.h>
#include <cuda_fp8.h>
#include <cstdint>

#define B_   4
#define H_   32
#define W_   32
#define C_   64
#define F_   128
#define NF   8
#define KC   (C_ * NF)       // 512 fp8 bytes per kernel position
#define KTOT (9 * KC)        // 4608
#define HP   34
#define WP   34
#define NPIX (B_ * H_ * W_)  // 4096
#define NOUT (NPIX * F_)     // 524288

#define LDB  144             // smem row stride in BYTES

// Scratch (device globals — no allocation)
__device__ __align__(16) uint8_t g_Xf[B_ * HP * WP * KC]; // ~2.4 MB e4m3
__device__ __align__(16) uint8_t g_Wt[F_ * KTOT];         // ~0.6 MB e4m3
__device__ unsigned g_Cnt[64];                            // per-M-tile completion counters

__device__ __forceinline__ int load_bits(const int* bp) {
    if (bp == nullptr) return 4;
    int b = bp[0];
    if (b < 1 || b > 30) b = (int)__int_as_float(b);
    if (b < 1 || b > 30) b = 4;
    return b;
}

// e4m3 encodings of integers 0..7 and 8..15 (all exact in e4m3)
#define E4M3_LUT0 0x4E4C4A4844403800ull
#define E4M3_LUT1 0x5756555453525150ull

__device__ __forceinline__ uint32_t int_to_e4m3(int v) {
    if (v < 8)  return (uint32_t)((E4M3_LUT0 >> (v * 8)) & 0xFF);
    if (v < 16) return (uint32_t)((E4M3_LUT1 >> ((v - 8) * 8)) & 0xFF);
    return (uint32_t)__nv_cvt_float_to_fp8((float)v, __NV_SATFINITE, __NV_E4M3);
}

#define FEAT_TOTAL (B_ * HP * WP * C_)   // 295936
#define WT_TOTAL   (9 * C_ * F_)         // 73728
#define INIT_TOTAL (NOUT / 4)            // 131072
#define PREP_TOTAL (FEAT_TOTAL + WT_TOTAL + INIT_TOTAL + 64)

// ---------------------------------------------------------------------------
// Fused prep: feature expand (e4m3 LUT) + weight expand + out=bias + counters.
// ---------------------------------------------------------------------------
__global__ void prep_kernel(const float* __restrict__ x, const float* __restrict__ kern,
                            const float4* __restrict__ bias4, float4* __restrict__ out4,
                            const int* __restrict__ bitsPtr) {
    int idx = blockIdx.x * blockDim.x + threadIdx.x;
    if (idx >= PREP_TOTAL) return;
    int bits = load_bits(bitsPtr);

    if (idx < FEAT_TOTAL) {
        int c  = idx & (C_ - 1);
        int r  = idx >> 6;
        int wp = r % WP; r /= WP;
        int hp = r % HP;
        int b  = r / HP;

        uint64_t pack = 0;
        if (hp >= 1 && hp <= H_ && wp >= 1 && wp <= W_) {
            int xi = (int)x[(((b * H_) + (hp - 1)) * W_ + (wp - 1)) * C_ + c];
#pragma unroll
            for (int m = 1; m <= 8; m++)
                pack |= (uint64_t)int_to_e4m3((xi * m) >> bits) << (8 * (m - 1));
        }
        reinterpret_cast<uint64_t*>(g_Xf)[idx] = pack;
    } else if (idx < FEAT_TOTAL + WT_TOTAL) {
        int i = idx - FEAT_TOTAL;
        int mask = (1 << bits) - 1;
        int f   = i & (F_ - 1);
        int r   = i >> 7;
        int c   = r & (C_ - 1);
        int pos = r >> 6;

        int wi = (int)kern[i];
        int s  = (wi > 0) - (wi < 0);
        int m  = (wi < 0 ? -wi : wi) & mask;

        uint64_t pack = 0;
        if (m >= 1 && m <= 8)
            pack = (uint64_t)(s > 0 ? 0x38u : 0xB8u) << (8 * (m - 1)); // ±1 e4m3
        reinterpret_cast<uint64_t*>(g_Wt)[f * (KTOT / 8) + pos * (KC / 8) + c] = pack;
    } else if (idx < FEAT_TOTAL + WT_TOTAL + INIT_TOTAL) {
        int t = idx - FEAT_TOTAL - WT_TOTAL;
        out4[t] = bias4[t & 31];
    } else {
        g_Cnt[idx - FEAT_TOTAL - WT_TOTAL - INIT_TOTAL] = 0;   // reset every replay
    }
}

// ---------------------------------------------------------------------------
// FP8 GEMM (R5 core, unchanged): block 64(M) x 128(N), 8 warps 2x4, grid
// (64, 9). mma m16n8k32 e4m3 -> f32. cp.async double buffer, 4 x 128B slabs.
// Fused tail: 9th CTA per M-tile applies bias-already-added relu in place.
// ---------------------------------------------------------------------------
__device__ __forceinline__ void mma_e4m3(float c[4], const uint32_t a[4], const uint32_t b0,
                                         const uint32_t b1) {
    asm volatile(
        "mma.sync.aligned.m16n8k32.row.col.f32.e4m3.e4m3.f32 "
        "{%0,%1,%2,%3}, {%4,%5,%6,%7}, {%8,%9}, {%0,%1,%2,%3};\n"
        : "+f"(c[0]), "+f"(c[1]), "+f"(c[2]), "+f"(c[3])
        : "r"(a[0]), "r"(a[1]), "r"(a[2]), "r"(a[3]), "r"(b0), "r"(b1));
}
__device__ __forceinline__ void ldsm_x4(uint32_t r[4], uint32_t addr) {
    asm volatile("ldmatrix.sync.aligned.m8n8.x4.shared.b16 {%0,%1,%2,%3}, [%4];"
                 : "=r"(r[0]), "=r"(r[1]), "=r"(r[2]), "=r"(r[3]) : "r"(addr));
}
__device__ __forceinline__ void cp16(uint32_t smemAddr, const void* gmem) {
    asm volatile("cp.async.cg.shared.global [%0], [%1], 16;" :: "r"(smemAddr), "l"(gmem));
}

#define ASLAB (64 * LDB)     // bytes per A buffer (64 rows)
#define BSLAB (128 * LDB)    // bytes per B buffer (128 rows)
#define SMEMB (2 * ASLAB + 2 * BSLAB)   // 55296 bytes

__global__ __launch_bounds__(256, 3) void gemm_kernel(float* __restrict__ out) {
    extern __shared__ uint8_t sm[];
    uint8_t* As = sm;               // [2][64][LDB]
    uint8_t* Bs = sm + 2 * ASLAB;   // [2][128][LDB]
    __shared__ unsigned lastFlag;

    const int tid = threadIdx.x;
    const int pos = blockIdx.y;
    const int di  = pos / 3, dj = pos - di * 3;
    const int p0  = blockIdx.x * 64;

    const int cr = tid >> 3;          // 0..31
    const int cc = tid & 7;           // 16B chunk within 128B row
    const uint8_t* aSrc[2];
    const uint8_t* bSrc[4];
    uint32_t aDst[2], bDst[4];
#pragma unroll
    for (int ps = 0; ps < 2; ps++) {
        int r = cr + ps * 32;
        int p = p0 + r;
        int bb = p >> 10, hh = (p >> 5) & 31, ww = p & 31;
        aSrc[ps] = g_Xf + ((bb * HP + hh + di) * WP + (ww + dj)) * KC + cc * 16;
        aDst[ps] = (uint32_t)__cvta_generic_to_shared(As + r * LDB + cc * 16);
    }
#pragma unroll
    for (int ps = 0; ps < 4; ps++) {
        int r = cr + ps * 32;
        bSrc[ps] = g_Wt + r * KTOT + pos * KC + cc * 16;
        bDst[ps] = (uint32_t)__cvta_generic_to_shared(Bs + r * LDB + cc * 16);
    }

    const int wa = tid >> 5, lane = tid & 31;
    const int wm = wa & 1, wn = wa >> 1;
    const int fRow  = lane & 15;
    const int fColB = (lane >> 4) << 4;

    float acc[2][4][4];
#pragma unroll
    for (int mi = 0; mi < 2; mi++)
#pragma unroll
        for (int j = 0; j < 4; j++)
#pragma unroll
            for (int e = 0; e < 4; e++) acc[mi][j][e] = 0.0f;

#pragma unroll
    for (int ps = 0; ps < 2; ps++) cp16(aDst[ps], aSrc[ps]);
#pragma unroll
    for (int ps = 0; ps < 4; ps++) cp16(bDst[ps], bSrc[ps]);
    asm volatile("cp.async.commit_group;");

#pragma unroll 1
    for (int ks = 0; ks < 4; ks++) {
        const int cur = ks & 1;
        if (ks < 3) {
            const int nxt = (ks + 1) & 1;
            const int k0 = (ks + 1) * 128;
#pragma unroll
            for (int ps = 0; ps < 2; ps++) cp16(aDst[ps] + nxt * ASLAB, aSrc[ps] + k0);
#pragma unroll
            for (int ps = 0; ps < 4; ps++) cp16(bDst[ps] + nxt * BSLAB, bSrc[ps] + k0);
            asm volatile("cp.async.commit_group;");
            asm volatile("cp.async.wait_group 1;");
        } else {
            asm volatile("cp.async.wait_group 0;");
        }
        __syncthreads();

        const uint8_t* Ab = As + cur * ASLAB;
        const uint8_t* Bb = Bs + cur * BSLAB;
#pragma unroll
        for (int kk = 0; kk < 4; kk++) {
            const int kcB = kk * 32;
            uint32_t a[2][4], b[2][4];
#pragma unroll
            for (int mi = 0; mi < 2; mi++) {
                uint32_t ad = (uint32_t)__cvta_generic_to_shared(
                    Ab + (wm * 32 + mi * 16 + fRow) * LDB + kcB + fColB);
                ldsm_x4(a[mi], ad);
            }
#pragma unroll
            for (int ni = 0; ni < 2; ni++) {
                uint32_t bd = (uint32_t)__cvta_generic_to_shared(
                    Bb + (wn * 32 + ni * 16 + fRow) * LDB + kcB + fColB);
                ldsm_x4(b[ni], bd);
            }
#pragma unroll
            for (int mi = 0; mi < 2; mi++)
#pragma unroll
                for (int j = 0; j < 4; j++)
                    mma_e4m3(acc[mi][j], a[mi], b[j >> 1][j & 1], b[j >> 1][(j & 1) + 2]);
        }
        __syncthreads();
    }

    // ---- split-K epilogue: exact-integer f32 atomics ----
    const int g = lane >> 2, t4 = lane & 3;
#pragma unroll
    for (int mi = 0; mi < 2; mi++) {
        int r0 = p0 + wm * 32 + mi * 16 + g;
#pragma unroll
        for (int j = 0; j < 4; j++) {
            int ccol = wn * 32 + j * 8 + t4 * 2;
            atomicAdd(&out[r0 * F_ + ccol],           acc[mi][j][0]);
            atomicAdd(&out[r0 * F_ + ccol + 1],       acc[mi][j][1]);
            atomicAdd(&out[(r0 + 8) * F_ + ccol],     acc[mi][j][2]);
            atomicAdd(&out[(r0 + 8) * F_ + ccol + 1], acc[mi][j][3]);
        }
    }

    // ---- fused relu: last of the 9 CTAs for this M-tile applies relu ----
    __threadfence();                    // make this CTA's atomics visible
    __syncthreads();
    if (tid == 0) {
        unsigned old = atomicAdd(&g_Cnt[blockIdx.x], 1u);
        lastFlag = (old == 8u);
    }
    __syncthreads();
    if (lastFlag) {
        __threadfence();
        float4* o4 = (float4*)(out + (size_t)p0 * F_);
#pragma unroll
        for (int i = 0; i < (64 * F_ / 4) / 256; i++) {   // 8 float4 per thread
            float4 v = __ldcg(&o4[tid + i * 256]);
            v.x = fmaxf(v.x, 0.f); v.y = fmaxf(v.y, 0.f);
            v.z = fmaxf(v.z, 0.f); v.w = fmaxf(v.w, 0.f);
            o4[tid + i * 256] = v;
        }
    }
}

// ---------------------------------------------------------------------------
extern "C" void kernel_launch(void* const* d_in, const int* in_sizes, int n_in,
                              void* d_out, int out_size) {
    const float* x    = (const float*)d_in[0];
    const float* kern = (const float*)d_in[1];
    const float* bias = (const float*)d_in[2];
    const int*   bits = (n_in >= 4) ? (const int*)d_in[3] : nullptr;
    float* out = (float*)d_out;

    static int smemSet = 0;
    if (!smemSet) {
        cudaFuncSetAttribute(gemm_kernel, cudaFuncAttributeMaxDynamicSharedMemorySize, SMEMB);
        smemSet = 1;
    }

    prep_kernel<<<(PREP_TOTAL + 255) / 256, 256>>>(x, kern, (const float4*)bias,
                                                   (float4*)out, bits);
    dim3 gg(NPIX / 64, 9);
    gemm_kernel<<<gg, 256, SMEMB>>>(out);
}

// round 11
// speedup vs baseline: 1.5497x; 1.5497x over previous
#include <cuda_runtime.h>
#include <cuda_fp8.h>
#include <cstdint>

#define B_   4
#define H_   32
#define W_   32
#define C_   64
#define F_   128
#define NF   8
#define KC   (C_ * NF)       // 512 fp8 bytes per kernel position
#define KTOT (9 * KC)        // 4608
#define HP   34
#define WP   34
#define NPIX (B_ * H_ * W_)  // 4096
#define NOUT (NPIX * F_)     // 524288

#define LDB  144             // smem row stride in BYTES

// Scratch (device globals — no allocation)
__device__ __align__(16) uint8_t g_Xf[B_ * HP * WP * KC]; // ~2.4 MB e4m3
__device__ __align__(16) uint8_t g_Wt[F_ * KTOT];         // ~0.6 MB e4m3

__device__ __forceinline__ int load_bits(const int* bp) {
    if (bp == nullptr) return 4;
    int b = bp[0];
    if (b < 1 || b > 30) b = (int)__int_as_float(b);
    if (b < 1 || b > 30) b = 4;
    return b;
}

// e4m3 encodings of integers 0..7 and 8..15 (all exact in e4m3)
#define E4M3_LUT0 0x4E4C4A4844403800ull
#define E4M3_LUT1 0x5756555453525150ull

__device__ __forceinline__ uint32_t int_to_e4m3(int v) {
    if (v < 8)  return (uint32_t)((E4M3_LUT0 >> (v * 8)) & 0xFF);
    if (v < 16) return (uint32_t)((E4M3_LUT1 >> ((v - 8) * 8)) & 0xFF);
    return (uint32_t)__nv_cvt_float_to_fp8((float)v, __NV_SATFINITE, __NV_E4M3);
}

#define FEAT_TOTAL (B_ * HP * WP * C_)   // 295936
#define WT_TOTAL   (9 * C_ * F_)         // 73728
#define INIT_TOTAL (NOUT / 4)            // 131072
#define PREP_TOTAL (FEAT_TOTAL + WT_TOTAL + INIT_TOTAL)

// ---------------------------------------------------------------------------
// Fused prep: feature expand (e4m3 LUT) + weight expand + out=bias init.
// ---------------------------------------------------------------------------
__global__ void prep_kernel(const float* __restrict__ x, const float* __restrict__ kern,
                            const float4* __restrict__ bias4, float4* __restrict__ out4,
                            const int* __restrict__ bitsPtr) {
    int idx = blockIdx.x * blockDim.x + threadIdx.x;
    if (idx >= PREP_TOTAL) return;
    int bits = load_bits(bitsPtr);

    if (idx < FEAT_TOTAL) {
        int c  = idx & (C_ - 1);
        int r  = idx >> 6;
        int wp = r % WP; r /= WP;
        int hp = r % HP;
        int b  = r / HP;

        uint64_t pack = 0;
        if (hp >= 1 && hp <= H_ && wp >= 1 && wp <= W_) {
            int xi = (int)x[(((b * H_) + (hp - 1)) * W_ + (wp - 1)) * C_ + c];
#pragma unroll
            for (int m = 1; m <= 8; m++)
                pack |= (uint64_t)int_to_e4m3((xi * m) >> bits) << (8 * (m - 1));
        }
        reinterpret_cast<uint64_t*>(g_Xf)[idx] = pack;
    } else if (idx < FEAT_TOTAL + WT_TOTAL) {
        int i = idx - FEAT_TOTAL;
        int mask = (1 << bits) - 1;
        int f   = i & (F_ - 1);
        int r   = i >> 7;
        int c   = r & (C_ - 1);
        int pos = r >> 6;

        int wi = (int)kern[i];
        int s  = (wi > 0) - (wi < 0);
        int m  = (wi < 0 ? -wi : wi) & mask;

        uint64_t pack = 0;
        if (m >= 1 && m <= 8)
            pack = (uint64_t)(s > 0 ? 0x38u : 0xB8u) << (8 * (m - 1)); // ±1 e4m3
        reinterpret_cast<uint64_t*>(g_Wt)[f * (KTOT / 8) + pos * (KC / 8) + c] = pack;
    } else {
        int t = idx - FEAT_TOTAL - WT_TOTAL;
        out4[t] = bias4[t & 31];
    }
}

__global__ void relu_kernel(float4* __restrict__ out) {
    int t = blockIdx.x * blockDim.x + threadIdx.x;
    if (t >= NOUT / 4) return;
    float4 v = out[t];
    v.x = fmaxf(v.x, 0.f); v.y = fmaxf(v.y, 0.f);
    v.z = fmaxf(v.z, 0.f); v.w = fmaxf(v.w, 0.f);
    out[t] = v;
}

// ---------------------------------------------------------------------------
// FP8 GEMM (R5 core, verbatim): block 64(M) x 128(N), 8 warps 2x4, grid
// (64, 9). mma m16n8k32 e4m3 -> f32 (exact). cp.async double buffer.
// ---------------------------------------------------------------------------
__device__ __forceinline__ void mma_e4m3(float c[4], const uint32_t a[4], const uint32_t b0,
                                         const uint32_t b1) {
    asm volatile(
        "mma.sync.aligned.m16n8k32.row.col.f32.e4m3.e4m3.f32 "
        "{%0,%1,%2,%3}, {%4,%5,%6,%7}, {%8,%9}, {%0,%1,%2,%3};\n"
        : "+f"(c[0]), "+f"(c[1]), "+f"(c[2]), "+f"(c[3])
        : "r"(a[0]), "r"(a[1]), "r"(a[2]), "r"(a[3]), "r"(b0), "r"(b1));
}
__device__ __forceinline__ void ldsm_x4(uint32_t r[4], uint32_t addr) {
    asm volatile("ldmatrix.sync.aligned.m8n8.x4.shared.b16 {%0,%1,%2,%3}, [%4];"
                 : "=r"(r[0]), "=r"(r[1]), "=r"(r[2]), "=r"(r[3]) : "r"(addr));
}
__device__ __forceinline__ void cp16(uint32_t smemAddr, const void* gmem) {
    asm volatile("cp.async.cg.shared.global [%0], [%1], 16;" :: "r"(smemAddr), "l"(gmem));
}

#define ASLAB (64 * LDB)     // bytes per A buffer (64 rows)
#define BSLAB (128 * LDB)    // bytes per B buffer (128 rows)
#define SMEMB (2 * ASLAB + 2 * BSLAB)   // 55296 bytes

__global__ __launch_bounds__(256, 3) void gemm_kernel(float* __restrict__ out) {
    extern __shared__ uint8_t sm[];
    uint8_t* As = sm;               // [2][64][LDB]
    uint8_t* Bs = sm + 2 * ASLAB;   // [2][128][LDB]

    const int tid = threadIdx.x;
    const int pos = blockIdx.y;
    const int di  = pos / 3, dj = pos - di * 3;
    const int p0  = blockIdx.x * 64;

    const int cr = tid >> 3;          // 0..31
    const int cc = tid & 7;           // 16B chunk within 128B row
    const uint8_t* aSrc[2];
    const uint8_t* bSrc[4];
    uint32_t aDst[2], bDst[4];
#pragma unroll
    for (int ps = 0; ps < 2; ps++) {
        int r = cr + ps * 32;
        int p = p0 + r;
        int bb = p >> 10, hh = (p >> 5) & 31, ww = p & 31;
        aSrc[ps] = g_Xf + ((bb * HP + hh + di) * WP + (ww + dj)) * KC + cc * 16;
        aDst[ps] = (uint32_t)__cvta_generic_to_shared(As + r * LDB + cc * 16);
    }
#pragma unroll
    for (int ps = 0; ps < 4; ps++) {
        int r = cr + ps * 32;
        bSrc[ps] = g_Wt + r * KTOT + pos * KC + cc * 16;
        bDst[ps] = (uint32_t)__cvta_generic_to_shared(Bs + r * LDB + cc * 16);
    }

    const int wa = tid >> 5, lane = tid & 31;
    const int wm = wa & 1, wn = wa >> 1;
    const int fRow  = lane & 15;
    const int fColB = (lane >> 4) << 4;

    float acc[2][4][4];
#pragma unroll
    for (int mi = 0; mi < 2; mi++)
#pragma unroll
        for (int j = 0; j < 4; j++)
#pragma unroll
            for (int e = 0; e < 4; e++) acc[mi][j][e] = 0.0f;

#pragma unroll
    for (int ps = 0; ps < 2; ps++) cp16(aDst[ps], aSrc[ps]);
#pragma unroll
    for (int ps = 0; ps < 4; ps++) cp16(bDst[ps], bSrc[ps]);
    asm volatile("cp.async.commit_group;");

#pragma unroll 1
    for (int ks = 0; ks < 4; ks++) {
        const int cur = ks & 1;
        if (ks < 3) {
            const int nxt = (ks + 1) & 1;
            const int k0 = (ks + 1) * 128;
#pragma unroll
            for (int ps = 0; ps < 2; ps++) cp16(aDst[ps] + nxt * ASLAB, aSrc[ps] + k0);
#pragma unroll
            for (int ps = 0; ps < 4; ps++) cp16(bDst[ps] + nxt * BSLAB, bSrc[ps] + k0);
            asm volatile("cp.async.commit_group;");
            asm volatile("cp.async.wait_group 1;");
        } else {
            asm volatile("cp.async.wait_group 0;");
        }
        __syncthreads();

        const uint8_t* Ab = As + cur * ASLAB;
        const uint8_t* Bb = Bs + cur * BSLAB;
#pragma unroll
        for (int kk = 0; kk < 4; kk++) {
            const int kcB = kk * 32;
            uint32_t a[2][4], b[2][4];
#pragma unroll
            for (int mi = 0; mi < 2; mi++) {
                uint32_t ad = (uint32_t)__cvta_generic_to_shared(
                    Ab + (wm * 32 + mi * 16 + fRow) * LDB + kcB + fColB);
                ldsm_x4(a[mi], ad);
            }
#pragma unroll
            for (int ni = 0; ni < 2; ni++) {
                uint32_t bd = (uint32_t)__cvta_generic_to_shared(
                    Bb + (wn * 32 + ni * 16 + fRow) * LDB + kcB + fColB);
                ldsm_x4(b[ni], bd);
            }
#pragma unroll
            for (int mi = 0; mi < 2; mi++)
#pragma unroll
                for (int j = 0; j < 4; j++)
                    mma_e4m3(acc[mi][j], a[mi], b[j >> 1][j & 1], b[j >> 1][(j & 1) + 2]);
        }
        __syncthreads();
    }

    // ---- split-K epilogue: exact-integer f32 atomics ----
    const int g = lane >> 2, t4 = lane & 3;
#pragma unroll
    for (int mi = 0; mi < 2; mi++) {
        int r0 = p0 + wm * 32 + mi * 16 + g;
#pragma unroll
        for (int j = 0; j < 4; j++) {
            int ccol = wn * 32 + j * 8 + t4 * 2;
            atomicAdd(&out[r0 * F_ + ccol],           acc[mi][j][0]);
            atomicAdd(&out[r0 * F_ + ccol + 1],       acc[mi][j][1]);
            atomicAdd(&out[(r0 + 8) * F_ + ccol],     acc[mi][j][2]);
            atomicAdd(&out[(r0 + 8) * F_ + ccol + 1], acc[mi][j][3]);
        }
    }
}

// ---------------------------------------------------------------------------
extern "C" void kernel_launch(void* const* d_in, const int* in_sizes, int n_in,
                              void* d_out, int out_size) {
    const float* x    = (const float*)d_in[0];
    const float* kern = (const float*)d_in[1];
    const float* bias = (const float*)d_in[2];
    const int*   bits = (n_in >= 4) ? (const int*)d_in[3] : nullptr;
    float* out = (float*)d_out;

    static int smemSet = 0;
    if (!smemSet) {
        cudaFuncSetAttribute(gemm_kernel, cudaFuncAttributeMaxDynamicSharedMemorySize, SMEMB);
        smemSet = 1;
    }

    prep_kernel<<<(PREP_TOTAL + 255) / 256, 256>>>(x, kern, (const float4*)bias,
                                                   (float4*)out, bits);
    dim3 gg(NPIX / 64, 9);
    gemm_kernel<<<gg, 256, SMEMB>>>(out);
    relu_kernel<<<(NOUT / 4 + 255) / 256, 256>>>((float4*)out);
}